// round 4
// baseline (speedup 1.0000x reference)
#include <cuda_runtime.h>
#include <cstdint>

#define Bn   16
#define Nn   512
#define Rn   10
#define DE   256
#define DR   64
#define DOUT 256
#define INDIM 3200
#define RELS  320

// Zt[br][o][m]  (tf32-RN-rounded fp32), 84MB scratch
__device__ float g_Z[(size_t)Bn * Rn * DOUT * Nn];

#define PAD 36                      // A-tile smem row stride (floats)
#define TILE_FLOATS (128 * PAD)     // 4608 floats / buffer
#define BSTRIDE 260                 // k_z node-tile row stride (floats)

// ---- smem bytes ----
#define KM_SMEM_BYTES ((6 * TILE_FLOATS + 128) * 4)                 // ~111KB
#define KZ_SMEM_BYTES ((128 * BSTRIDE + 3 * TILE_FLOATS + Rn*128) * 4) // ~194KB

__device__ __forceinline__ uint32_t rtf32_u(float x) {
    uint32_t r; asm("cvt.rna.tf32.f32 %0, %1;" : "=r"(r) : "f"(x)); return r;
}
__device__ __forceinline__ float rtf32(float x) {
    return __uint_as_float(rtf32_u(x));
}

#define CP_ASYNC16(smem_u32, gptr) \
    asm volatile("cp.async.cg.shared.global [%0], [%1], 16;" \
                 :: "r"(smem_u32), "l"(gptr) : "memory")
#define CP_COMMIT() asm volatile("cp.async.commit_group;" ::: "memory")
#define CP_WAIT1()  asm volatile("cp.async.wait_group 1;" ::: "memory")
#define CP_WAIT0()  asm volatile("cp.async.wait_group 0;" ::: "memory")

__device__ __forceinline__ void mma8(float* c, const uint32_t* a, const uint32_t* b) {
    asm volatile(
        "mma.sync.aligned.m16n8k8.row.col.f32.tf32.tf32.f32 "
        "{%0,%1,%2,%3}, {%4,%5,%6,%7}, {%8,%9}, {%0,%1,%2,%3};"
        : "+f"(c[0]), "+f"(c[1]), "+f"(c[2]), "+f"(c[3])
        : "r"(a[0]), "r"(a[1]), "r"(a[2]), "r"(a[3]), "r"(b[0]), "r"(b[1]));
}

// A_chunk: [128 rows M][32 k] stride PAD.  B_chunk: [128 rows N][k] stride bs
// (already offset to the k-chunk).  Warp grid 4(M) x 2(N), warp tile 32x64.
__device__ __forceinline__ void compute_chunk(const float* __restrict__ A_chunk,
                                              const float* __restrict__ B_chunk,
                                              int bs, int wm, int wn, int lane,
                                              float (&acc)[2][8][4]) {
    const float* a_base = A_chunk + (wm * 32) * PAD;
    const float* b_base = B_chunk + (wn * 64) * bs;
    const int r4 = lane >> 2, c4 = lane & 3;
#pragma unroll
    for (int ks = 0; ks < 4; ks++) {
        const int k = ks * 8 + c4;
        uint32_t af[2][4];
#pragma unroll
        for (int mi = 0; mi < 2; mi++) {
            const float* ap = a_base + (mi * 16 + r4) * PAD + k;
            af[mi][0] = __float_as_uint(ap[0]);
            af[mi][1] = __float_as_uint(ap[8 * PAD]);
            af[mi][2] = __float_as_uint(ap[4]);
            af[mi][3] = __float_as_uint(ap[8 * PAD + 4]);
        }
        uint32_t bf[8][2];
#pragma unroll
        for (int ni = 0; ni < 8; ni++) {
            const float* bp = b_base + (ni * 8 + r4) * bs + k;
            bf[ni][0] = __float_as_uint(bp[0]);
            bf[ni][1] = __float_as_uint(bp[4]);
        }
#pragma unroll
        for (int mi = 0; mi < 2; mi++)
#pragma unroll
            for (int ni = 0; ni < 8; ni++)
                mma8(acc[mi][ni], af[mi], bf[ni]);
    }
}

// ---------------------------------------------------------------------------
// k_z: one CTA per (m-tile, o-tile, b); loops r internally, node tile SMEM-resident.
// Zt[br][o][m] = rtf32( (W_node_r @ node^T)[o][m] + v[r][o] )
// grid (4, 2, 16) = 128 CTAs, 256 threads.
// ---------------------------------------------------------------------------
__global__ __launch_bounds__(256, 1) void k_z(const float* __restrict__ node,
                                              const float* __restrict__ rel,
                                              const float* __restrict__ W) {
    extern __shared__ float sm[];
    float* Bnode = sm;                                  // 128 x BSTRIDE
    float* As    = sm + 128 * BSTRIDE;                  // 3 bufs
    float* vs    = sm + 128 * BSTRIDE + 3 * TILE_FLOATS; // [Rn][128]

    const int tid = threadIdx.x, lane = tid & 31, warp = tid >> 5;
    const int wm = warp & 3, wn = warp >> 2;
    const int b = blockIdx.z;
    const int mm0 = blockIdx.x * 128;   // N-dim (m)
    const int o0  = blockIdx.y * 128;   // M-dim (o)
    const int lrow = tid >> 3, lq = (tid & 7) * 4;

    // Stage node tile [128 m][256 d], tf32-RN rounded, stride BSTRIDE.
#pragma unroll 8
    for (int i = 0; i < 32; i++) {
        const int g = i * 256 + tid;
        const int row = g >> 6, c4 = g & 63;
        float4 v = *reinterpret_cast<const float4*>(
            node + ((size_t)(b * Nn + mm0 + row)) * DE + c4 * 4);
        v.x = rtf32(v.x); v.y = rtf32(v.y); v.z = rtf32(v.z); v.w = rtf32(v.w);
        *reinterpret_cast<float4*>(Bnode + row * BSTRIDE + c4 * 4) = v;
    }
    // v[r][o] = rel[b,r,:] . W[o, r*320+256 .. +64)
    if (tid < 128) {
        for (int r = 0; r < Rn; r++) {
            const float* wr = W + (size_t)(o0 + tid) * INDIM + r * RELS + DE;
            const float* rp = rel + (size_t)(b * Rn + r) * DR;
            float s = 0.f;
#pragma unroll
            for (int d = 0; d < DR; d++) s += rp[d] * wr[d];
            vs[r * 128 + tid] = s;
        }
    }

    float acc[2][8][4];
#pragma unroll
    for (int mi = 0; mi < 2; mi++)
#pragma unroll
        for (int ni = 0; ni < 8; ni++)
#pragma unroll
            for (int q = 0; q < 4; q++) acc[mi][ni][q] = 0.f;

    float4 va[4];
    auto ldgA = [&](int j) {
        const int r = j >> 3, kk = j & 7;
        const float* Ab = W + (size_t)o0 * INDIM + r * RELS + kk * 32;
#pragma unroll
        for (int i = 0; i < 4; i++)
            va[i] = *reinterpret_cast<const float4*>(
                Ab + (size_t)(i * 32 + lrow) * INDIM + lq);
    };
    auto stsA = [&](int buf) {
        float* ad = As + buf * TILE_FLOATS;
#pragma unroll
        for (int i = 0; i < 4; i++) {
            float4 a = va[i];
            a.x = rtf32(a.x); a.y = rtf32(a.y); a.z = rtf32(a.z); a.w = rtf32(a.w);
            *reinterpret_cast<float4*>(ad + (i * 32 + lrow) * PAD + lq) = a;
        }
    };

    ldgA(0); stsA(0); ldgA(1);

    const int J = Rn * 8;  // 80
    const int r4 = lane >> 2, c2 = 2 * (lane & 3);
    for (int j = 0; j < J; j++) {
        __syncthreads();
        if (j + 1 < J) stsA((j + 1) % 3);
        if (j + 2 < J) ldgA(j + 2);
        compute_chunk(As + (j % 3) * TILE_FLOATS, Bnode + (j & 7) * 32,
                      BSTRIDE, wm, wn, lane, acc);
        if ((j & 7) == 7) {
            const int r = j >> 3;
            float* zr = g_Z + (size_t)(b * Rn + r) * (DOUT * Nn);
#pragma unroll
            for (int mi = 0; mi < 2; mi++) {
#pragma unroll
                for (int ni = 0; ni < 8; ni++) {
                    const int orow = wm * 32 + mi * 16 + r4;
                    const int mcol = wn * 64 + ni * 8 + c2;
                    float* zp = zr + (size_t)(o0 + orow) * Nn + mm0 + mcol;
                    const float v0 = vs[r * 128 + orow];
                    float2 lo = { rtf32(acc[mi][ni][0] + v0), rtf32(acc[mi][ni][1] + v0) };
                    *reinterpret_cast<float2*>(zp) = lo;
                    const float v1 = vs[r * 128 + orow + 8];
                    float2 hi = { rtf32(acc[mi][ni][2] + v1), rtf32(acc[mi][ni][3] + v1) };
                    *reinterpret_cast<float2*>(zp + (size_t)8 * Nn) = hi;
#pragma unroll
                    for (int q = 0; q < 4; q++) acc[mi][ni][q] = 0.f;
                }
            }
        }
    }
}

// ---------------------------------------------------------------------------
// k_main: out[b][n][o] = bias[o] + sum_{r,m} adj[b,r,n,m] * Zt[br][o][m]
// K = 5120 in 160 chunks.  A: LDG+cvt.rna+STS (3-buf).  B: cp.async (3-buf).
// grid (4, 2, 16) = 128 CTAs, 256 threads.
// ---------------------------------------------------------------------------
__global__ __launch_bounds__(256, 1) void k_main(const float* __restrict__ adj,
                                                 const float* __restrict__ bias,
                                                 float* __restrict__ out) {
    extern __shared__ float sm[];
    float* As  = sm;                         // 3 bufs
    float* Bs  = sm + 3 * TILE_FLOATS;       // 3 bufs
    float* bsm = sm + 6 * TILE_FLOATS;       // 128

    const int tid = threadIdx.x, lane = tid & 31, warp = tid >> 5;
    const int wm = warp & 3, wn = warp >> 2;
    const int b = blockIdx.z;
    const int n0 = blockIdx.x * 128, o0 = blockIdx.y * 128;
    const int lrow = tid >> 3, lq = (tid & 7) * 4;

    if (tid < 128) bsm[tid] = bias[o0 + tid];

    float acc[2][8][4];
#pragma unroll
    for (int mi = 0; mi < 2; mi++)
#pragma unroll
        for (int ni = 0; ni < 8; ni++)
#pragma unroll
            for (int q = 0; q < 4; q++) acc[mi][ni][q] = 0.f;

    float4 va[4];
    auto ldgA = [&](int j) {
        const int r = j >> 4, kk = j & 15;
        const float* Ab = adj + (size_t)(b * Rn + r) * (Nn * Nn) + (size_t)n0 * Nn + kk * 32;
#pragma unroll
        for (int i = 0; i < 4; i++)
            va[i] = *reinterpret_cast<const float4*>(Ab + (size_t)(i * 32 + lrow) * Nn + lq);
    };
    auto stsA = [&](int buf) {
        float* ad = As + buf * TILE_FLOATS;
#pragma unroll
        for (int i = 0; i < 4; i++) {
            float4 a = va[i];
            a.x = rtf32(a.x); a.y = rtf32(a.y); a.z = rtf32(a.z); a.w = rtf32(a.w);
            *reinterpret_cast<float4*>(ad + (i * 32 + lrow) * PAD + lq) = a;
        }
    };
    auto cpB = [&](int j) {
        const int r = j >> 4, kk = j & 15;
        const float* Bb = g_Z + (size_t)(b * Rn + r) * (DOUT * Nn) + (size_t)o0 * Nn + kk * 32;
        float* bd = Bs + (j % 3) * TILE_FLOATS;
#pragma unroll
        for (int i = 0; i < 4; i++) {
            uint32_t sdst = (uint32_t)__cvta_generic_to_shared(
                bd + (i * 32 + lrow) * PAD + lq);
            CP_ASYNC16(sdst, Bb + (size_t)(i * 32 + lrow) * Nn + lq);
        }
        CP_COMMIT();
    };

    // Prologue: groups 0 and 1 committed; va holds chunk 1.
    ldgA(0); stsA(0);
    cpB(0);  cpB(1);
    ldgA(1);

    const int J = 160;
    for (int j = 0; j < J; j++) {
        if (j < J - 1) CP_WAIT1(); else CP_WAIT0();   // group j complete
        __syncthreads();                               // B(j)/A(j) visible; bufs free
        if (j + 1 < J) stsA((j + 1) % 3);
        if (j + 2 < J) { cpB(j + 2); ldgA(j + 2); }
        compute_chunk(As + (j % 3) * TILE_FLOATS, Bs + (j % 3) * TILE_FLOATS,
                      PAD, wm, wn, lane, acc);
    }

    const int r4 = lane >> 2, c2 = 2 * (lane & 3);
#pragma unroll
    for (int mi = 0; mi < 2; mi++) {
#pragma unroll
        for (int ni = 0; ni < 8; ni++) {
            const int nrow = wm * 32 + mi * 16 + r4;
            const int ocol = wn * 64 + ni * 8 + c2;
            float* op = out + ((size_t)(b * Nn + n0 + nrow)) * DOUT + o0 + ocol;
            float2 lo = { acc[mi][ni][0] + bsm[ocol], acc[mi][ni][1] + bsm[ocol + 1] };
            *reinterpret_cast<float2*>(op) = lo;
            float2 hi = { acc[mi][ni][2] + bsm[ocol], acc[mi][ni][3] + bsm[ocol + 1] };
            *reinterpret_cast<float2*>(op + (size_t)8 * DOUT) = hi;
        }
    }
}

// ---------------------------------------------------------------------------
extern "C" void kernel_launch(void* const* d_in, const int* in_sizes, int n_in,
                              void* d_out, int out_size) {
    const float *node = nullptr, *rel = nullptr, *adj = nullptr,
                *W = nullptr, *bias = nullptr;
    for (int i = 0; i < n_in; i++) {
        const int s = in_sizes[i];
        if      (s == Bn * Nn * DE)      node = (const float*)d_in[i];
        else if (s == Bn * Rn * DR)      rel  = (const float*)d_in[i];
        else if (s == Bn * Rn * Nn * Nn) adj  = (const float*)d_in[i];
        else if (s == DOUT * INDIM)      W    = (const float*)d_in[i];
        else if (s == DOUT)              bias = (const float*)d_in[i];
    }
    cudaFuncSetAttribute(k_z,    cudaFuncAttributeMaxDynamicSharedMemorySize, KZ_SMEM_BYTES);
    cudaFuncSetAttribute(k_main, cudaFuncAttributeMaxDynamicSharedMemorySize, KM_SMEM_BYTES);

    k_z   <<<dim3(4, 2, Bn), 256, KZ_SMEM_BYTES>>>(node, rel, W);
    k_main<<<dim3(4, 2, Bn), 256, KM_SMEM_BYTES>>>(adj, bias, (float*)d_out);
}